// round 2
// baseline (speedup 1.0000x reference)
#include <cuda_runtime.h>
#include <math.h>

// Problem dims
#define B_   1024
#define T_   256
#define D_   64
#define U_   512
#define HS   (B_*U_)     // 524288 floats per h/c buffer
#define N4   (4*U_)      // 2048 gate columns

// Tile config
#define BM 64            // batch rows per block
#define BU 32            // units per block (x4 gates => 128 z-cols)
#define BK 16            // K tile
#define NTHREADS 256

// Persistent state (device globals — no allocations allowed)
__device__ float g_h1[2*HS];
__device__ float g_c1[HS];
__device__ float g_h2[2*HS];
__device__ float g_c2[HS];

__device__ __forceinline__ float sigmoidf_(float x) {
    return 1.0f / (1.0f + __expf(-x));
}
__device__ __forceinline__ float tanhf_(float x) {
    float y;
    asm("tanh.approx.f32 %0, %1;" : "=f"(y) : "f"(x));
    return y;
}

// Packed fp32x2 FMA (Blackwell FFMA2: full-rate fp32 pipe, 2 MACs/instr)
#define FMA2(d, a, b) asm("fma.rn.f32x2 %0, %1, %2, %0;" : "+l"(d) : "l"(a), "l"(b))

// One LSTM layer step: z = x@W + h_prev@Uh + bias; gate update; writes h_out, c.
// layer==1 -> state g_h1/g_c1, layer==2 -> g_h2/g_c2 and x := g_h1[cur^1] (just written).
__global__ __launch_bounds__(NTHREADS, 2)
void lstm_step(const float* __restrict__ xext, int x_ld, int x_ktiles,
               const float* __restrict__ W,
               const float* __restrict__ Uh,
               const float* __restrict__ bias,
               int layer, int cur)
{
    __shared__ float sA[BK][BM + 4];     // +4 pad keeps 16B alignment, reduces bank conflicts
    __shared__ float sB[BK][BU][4];      // [k][unit][gate] — gate contiguous for packed loads

    float* hbase = (layer == 1) ? g_h1 : g_h2;
    float* cptr  = (layer == 1) ? g_c1 : g_c2;
    const float* hprev = hbase + (size_t)cur * HS;
    float*       hout  = hbase + (size_t)(cur ^ 1) * HS;
    const float* x = (layer == 2) ? (g_h1 + (size_t)(cur ^ 1) * HS) : xext;

    const int tid = threadIdx.x;
    const int tx  = tid & 15;    // unit-group: 2 units each
    const int ty  = tid >> 4;    // m-group: 4 rows each
    const int m0  = blockIdx.y * BM;
    const int u0  = blockIdx.x * BU;

    // acc[im][iu][p]: p=0 packs (i,f), p=1 packs (g,o)
    unsigned long long acc[4][2][2];
    #pragma unroll
    for (int a = 0; a < 4; a++)
        #pragma unroll
        for (int b = 0; b < 2; b++) { acc[a][b][0] = 0ull; acc[a][b][1] = 0ull; }

    const float* segA[2] = { x, hprev };
    const float* segW[2] = { W, Uh };
    const int    segLd[2] = { x_ld, U_ };
    const int    segKt[2] = { x_ktiles, U_ / BK };

    #pragma unroll
    for (int s = 0; s < 2; s++) {
        const float* A  = segA[s];
        const float* Wt = segW[s];
        const int lda = segLd[s];
        const int kt  = segKt[s];
        for (int t = 0; t < kt; t++) {
            const int k0 = t * BK;
            __syncthreads();
            // Load A tile (64 rows x 16 k), transposed into sA[k][m]
            {
                const int m = tid >> 2;
                const int q = tid & 3;
                float4 v = *reinterpret_cast<const float4*>(
                    &A[(size_t)(m0 + m) * lda + k0 + 4 * q]);
                sA[4*q+0][m] = v.x; sA[4*q+1][m] = v.y;
                sA[4*q+2][m] = v.z; sA[4*q+3][m] = v.w;
            }
            // Load weight tile for 4 gate column groups: sB[k][u][g]
            #pragma unroll
            for (int r = 0; r < 2; r++) {
                const int e = tid + r * NTHREADS;     // 512 float4 loads total
                const int k = e >> 5;
                const int g = (e >> 3) & 3;
                const int j = e & 7;
                float4 v = *reinterpret_cast<const float4*>(
                    &Wt[(size_t)(k0 + k) * N4 + g * U_ + u0 + 4 * j]);
                sB[k][4*j+0][g] = v.x; sB[k][4*j+1][g] = v.y;
                sB[k][4*j+2][g] = v.z; sB[k][4*j+3][g] = v.w;
            }
            __syncthreads();

            #pragma unroll
            for (int k = 0; k < BK; k++) {
                float4 av = *reinterpret_cast<const float4*>(&sA[k][4 * ty]);
                unsigned long long aa[4];
                asm("mov.b64 %0, {%1, %1};" : "=l"(aa[0]) : "r"(__float_as_uint(av.x)));
                asm("mov.b64 %0, {%1, %1};" : "=l"(aa[1]) : "r"(__float_as_uint(av.y)));
                asm("mov.b64 %0, {%1, %1};" : "=l"(aa[2]) : "r"(__float_as_uint(av.z)));
                asm("mov.b64 %0, {%1, %1};" : "=l"(aa[3]) : "r"(__float_as_uint(av.w)));
                // b: float4 (i,f,g,o) read as two packed b64: (i,f) and (g,o)
                ulonglong2 b0 = *reinterpret_cast<const ulonglong2*>(&sB[k][2*tx    ][0]);
                ulonglong2 b1 = *reinterpret_cast<const ulonglong2*>(&sB[k][2*tx + 1][0]);
                #pragma unroll
                for (int im = 0; im < 4; im++) {
                    FMA2(acc[im][0][0], aa[im], b0.x);
                    FMA2(acc[im][0][1], aa[im], b0.y);
                    FMA2(acc[im][1][0], aa[im], b1.x);
                    FMA2(acc[im][1][1], aa[im], b1.y);
                }
            }
        }
    }

    // Epilogue: LSTM cell update
    #pragma unroll
    for (int im = 0; im < 4; im++) {
        const int m = m0 + 4 * ty + im;
        #pragma unroll
        for (int iu = 0; iu < 2; iu++) {
            const int u = u0 + 2 * tx + iu;
            unsigned lo, hi;
            asm("mov.b64 {%0, %1}, %2;" : "=r"(lo), "=r"(hi) : "l"(acc[im][iu][0]));
            float zi = __uint_as_float(lo), zf = __uint_as_float(hi);
            asm("mov.b64 {%0, %1}, %2;" : "=r"(lo), "=r"(hi) : "l"(acc[im][iu][1]));
            float zg = __uint_as_float(lo), zo = __uint_as_float(hi);
            zi += bias[u];
            zf += bias[U_ + u];
            zg += bias[2 * U_ + u];
            zo += bias[3 * U_ + u];
            const size_t idx = (size_t)m * U_ + u;
            float c_old = cptr[idx];
            float c_new = sigmoidf_(zf) * c_old + sigmoidf_(zi) * tanhf_(zg);
            cptr[idx] = c_new;
            hout[idx] = sigmoidf_(zo) * tanhf_(c_new);
        }
    }
}

// Zero h1[buf0], c1, h2[buf0], c2 every invocation (graph replays must be deterministic)
__global__ void zero_state()
{
    const int i = blockIdx.x * blockDim.x + threadIdx.x;   // HS/4 = 131072 float4 lanes
    float4 z = make_float4(0.f, 0.f, 0.f, 0.f);
    reinterpret_cast<float4*>(g_h1)[i] = z;
    reinterpret_cast<float4*>(g_c1)[i] = z;
    reinterpret_cast<float4*>(g_h2)[i] = z;
    reinterpret_cast<float4*>(g_c2)[i] = z;
}

// out[b] = h2_final[b,:] @ Wd + bd   (final h2 lives in buffer 0 after t=255)
__global__ void dense_head(const float* __restrict__ Wd,
                           const float* __restrict__ bd,
                           float* __restrict__ out)
{
    const int warp = (blockIdx.x * blockDim.x + threadIdx.x) >> 5;
    const int lane = threadIdx.x & 31;
    if (warp >= B_) return;
    const float* h = g_h2 + (size_t)warp * U_;   // buffer 0
    float s = 0.f;
    #pragma unroll
    for (int k = lane; k < U_; k += 32) s += h[k] * Wd[k];
    #pragma unroll
    for (int off = 16; off; off >>= 1) s += __shfl_down_sync(0xffffffffu, s, off);
    if (lane == 0) out[warp] = s + bd[0];
}

extern "C" void kernel_launch(void* const* d_in, const int* in_sizes, int n_in,
                              void* d_out, int out_size)
{
    const float* inputs = (const float*)d_in[0];
    const float* W1  = (const float*)d_in[1];
    const float* Uh1 = (const float*)d_in[2];
    const float* b1  = (const float*)d_in[3];
    const float* W2  = (const float*)d_in[4];
    const float* Uh2 = (const float*)d_in[5];
    const float* b2  = (const float*)d_in[6];
    const float* Wd  = (const float*)d_in[7];
    const float* bd  = (const float*)d_in[8];
    float* out = (float*)d_out;

    zero_state<<<(HS / 4) / 256, 256>>>();

    dim3 grid(U_ / BU, B_ / BM);   // (16, 16) = 256 blocks
    for (int t = 0; t < T_; t++) {
        const int cur = t & 1;
        // layer 1: x = inputs[:, t, :] (row stride T*D), K1 = 64
        lstm_step<<<grid, NTHREADS>>>(inputs + (size_t)t * D_, T_ * D_, D_ / BK,
                                      W1, Uh1, b1, 1, cur);
        // layer 2: x = h1 just written (selected inside kernel), K1 = 512
        lstm_step<<<grid, NTHREADS>>>(nullptr, U_, U_ / BK,
                                      W2, Uh2, b2, 2, cur);
    }
    dense_head<<<(B_ * 32) / 256, 256>>>(Wd, bd, out);
}

// round 3
// speedup vs baseline: 1.5687x; 1.5687x over previous
#include <cuda_runtime.h>
#include <math.h>

// Problem dims
#define B_   1024
#define T_   256
#define D_   64
#define U_   512
#define HS   (B_*U_)
#define N4   (4*U_)      // 2048 gate columns

// Tile config: 128 blocks of 512 threads; per-thread 8 rows x 1 unit x 4 gates
#define BM 128
#define BU 32
#define BK 16
#define NT 512

// Persistent state (device globals — no allocations allowed)
__device__ float g_h1[2*HS];
__device__ float g_c1[HS];
__device__ float g_h2[2*HS];
__device__ float g_c2[HS];

__device__ __forceinline__ float sigmoidf_(float x) {
    return 1.0f / (1.0f + __expf(-x));
}
__device__ __forceinline__ float tanhf_(float x) {
    float y;
    asm("tanh.approx.f32 %0, %1;" : "=f"(y) : "f"(x));
    return y;
}

// Packed fp32x2 FMA (Blackwell FFMA2) and 32->64 duplicate pack
#define FMA2(d, a, b) asm("fma.rn.f32x2 %0, %1, %2, %0;" : "+l"(d) : "l"(a), "l"(b))
#define DUP2(d, x)    asm("mov.b64 %0, {%1, %1};" : "=l"(d) : "r"(__float_as_uint(x)))

// One LSTM layer step: z = x@W + h_prev@Uh + b; gate update; writes h_out, c.
__global__ __launch_bounds__(NT, 1)
void lstm_step(const float* __restrict__ xext, int x_ld, int x_tiles,
               const float* __restrict__ W,
               const float* __restrict__ Uh,
               const float* __restrict__ bias,
               int layer, int cur)
{
    __shared__ float sA[2][BK][BM];       // [buf][k][m]  (row-pairs read as b64 bcast)
    __shared__ float sB[2][BK][4][BU];    // [buf][k][gate][u]

    float* hbase = (layer == 1) ? g_h1 : g_h2;
    float* cptr  = (layer == 1) ? g_c1 : g_c2;
    const float* hprev = hbase + (size_t)cur * HS;
    float*       hout  = hbase + (size_t)(cur ^ 1) * HS;
    const float* x   = (layer == 2) ? (g_h1 + (size_t)(cur ^ 1) * HS) : xext;
    const int    xld = (layer == 2) ? U_ : x_ld;

    const int tid = threadIdx.x;
    const int tx  = tid & 31;             // unit within BU
    const int ty  = tid >> 5;             // row group (0..15), 8 rows each
    const int m0  = blockIdx.y * BM;
    const int u0  = blockIdx.x * BU;

    const int n_tiles = x_tiles + U_ / BK;

    // Stage-load index fields (conflict-free store patterns, verified):
    // A: 512 float4 per tile; lane m consecutive -> STS.32 banks all distinct
    const int am  = tid & 127;            // row
    const int akq = tid >> 7;             // k-quad 0..3
    // B: 512 float4 per tile; warp covers one k row, 512B contiguous STS.128
    const int buq = tid & 7;
    const int bgt = (tid >> 3) & 3;
    const int bkr = tid >> 5;

    // acc[row_pair][gate]: f32x2 = (row 8ty+2rp, row 8ty+2rp+1)
    unsigned long long acc[4][4];
    #pragma unroll
    for (int i = 0; i < 4; i++)
        #pragma unroll
        for (int j = 0; j < 4; j++) acc[i][j] = 0ull;

    float4 ra, rb;

    auto gload = [&](int tile) {
        const float* A; const float* Wt; int lda, kb;
        if (tile < x_tiles) { A = x;     Wt = W;  lda = xld; kb = tile * BK; }
        else                { A = hprev; Wt = Uh; lda = U_;  kb = (tile - x_tiles) * BK; }
        ra = *reinterpret_cast<const float4*>(&A[(size_t)(m0 + am) * lda + kb + 4 * akq]);
        rb = *reinterpret_cast<const float4*>(&Wt[(size_t)(kb + bkr) * N4 + bgt * U_ + u0 + 4 * buq]);
    };
    auto sstore = [&](int buf) {
        sA[buf][4*akq+0][am] = ra.x;
        sA[buf][4*akq+1][am] = ra.y;
        sA[buf][4*akq+2][am] = ra.z;
        sA[buf][4*akq+3][am] = ra.w;
        *reinterpret_cast<float4*>(&sB[buf][bkr][bgt][4*buq]) = rb;
    };
    auto compute = [&](int buf) {
        #pragma unroll
        for (int k = 0; k < BK; k++) {
            ulonglong2 aL = *reinterpret_cast<const ulonglong2*>(&sA[buf][k][8*ty]);
            ulonglong2 aH = *reinterpret_cast<const ulonglong2*>(&sA[buf][k][8*ty + 4]);
            unsigned long long b0, b1, b2, b3;
            DUP2(b0, sB[buf][k][0][tx]);
            DUP2(b1, sB[buf][k][1][tx]);
            DUP2(b2, sB[buf][k][2][tx]);
            DUP2(b3, sB[buf][k][3][tx]);
            FMA2(acc[0][0], aL.x, b0); FMA2(acc[0][1], aL.x, b1);
            FMA2(acc[0][2], aL.x, b2); FMA2(acc[0][3], aL.x, b3);
            FMA2(acc[1][0], aL.y, b0); FMA2(acc[1][1], aL.y, b1);
            FMA2(acc[1][2], aL.y, b2); FMA2(acc[1][3], aL.y, b3);
            FMA2(acc[2][0], aH.x, b0); FMA2(acc[2][1], aH.x, b1);
            FMA2(acc[2][2], aH.x, b2); FMA2(acc[2][3], aH.x, b3);
            FMA2(acc[3][0], aH.y, b0); FMA2(acc[3][1], aH.y, b1);
            FMA2(acc[3][2], aH.y, b2); FMA2(acc[3][3], aH.y, b3);
        }
    };

    gload(0);
    sstore(0);
    __syncthreads();
    int buf = 0;
    for (int t = 0; t < n_tiles; t++) {
        if (t + 1 < n_tiles) {
            gload(t + 1);
            compute(buf);
            __syncthreads();        // everyone done reading buf^1 (consumed at t-1)
            sstore(buf ^ 1);
            __syncthreads();        // stores visible before next compute
            buf ^= 1;
        } else {
            compute(buf);
        }
    }

    // Epilogue: LSTM cell update
    const int u = u0 + tx;
    const float bi_ = bias[u];
    const float bf_ = bias[U_ + u];
    const float bg_ = bias[2 * U_ + u];
    const float bo_ = bias[3 * U_ + u];
    #pragma unroll
    for (int rp = 0; rp < 4; rp++) {
        unsigned zi0, zi1, zf0, zf1, zg0, zg1, zo0, zo1;
        asm("mov.b64 {%0, %1}, %2;" : "=r"(zi0), "=r"(zi1) : "l"(acc[rp][0]));
        asm("mov.b64 {%0, %1}, %2;" : "=r"(zf0), "=r"(zf1) : "l"(acc[rp][1]));
        asm("mov.b64 {%0, %1}, %2;" : "=r"(zg0), "=r"(zg1) : "l"(acc[rp][2]));
        asm("mov.b64 {%0, %1}, %2;" : "=r"(zo0), "=r"(zo1) : "l"(acc[rp][3]));
        #pragma unroll
        for (int h = 0; h < 2; h++) {
            float zi = __uint_as_float(h ? zi1 : zi0) + bi_;
            float zf = __uint_as_float(h ? zf1 : zf0) + bf_;
            float zg = __uint_as_float(h ? zg1 : zg0) + bg_;
            float zo = __uint_as_float(h ? zo1 : zo0) + bo_;
            const int m = m0 + 8 * ty + 2 * rp + h;
            const size_t idx = (size_t)m * U_ + u;
            float c_old = cptr[idx];
            float c_new = sigmoidf_(zf) * c_old + sigmoidf_(zi) * tanhf_(zg);
            cptr[idx] = c_new;
            hout[idx] = sigmoidf_(zo) * tanhf_(c_new);
        }
    }
}

// Zero h1[buf0], c1, h2[buf0], c2 every invocation (graph replays deterministic)
__global__ void zero_state()
{
    const int i = blockIdx.x * blockDim.x + threadIdx.x;
    float4 z = make_float4(0.f, 0.f, 0.f, 0.f);
    reinterpret_cast<float4*>(g_h1)[i] = z;
    reinterpret_cast<float4*>(g_c1)[i] = z;
    reinterpret_cast<float4*>(g_h2)[i] = z;
    reinterpret_cast<float4*>(g_c2)[i] = z;
}

// out[b] = h2_final[b,:] @ Wd + bd   (final h2 in buffer 0 after t=255)
__global__ void dense_head(const float* __restrict__ Wd,
                           const float* __restrict__ bd,
                           float* __restrict__ out)
{
    const int warp = (blockIdx.x * blockDim.x + threadIdx.x) >> 5;
    const int lane = threadIdx.x & 31;
    if (warp >= B_) return;
    const float* h = g_h2 + (size_t)warp * U_;
    float s = 0.f;
    #pragma unroll
    for (int k = lane; k < U_; k += 32) s += h[k] * Wd[k];
    #pragma unroll
    for (int off = 16; off; off >>= 1) s += __shfl_down_sync(0xffffffffu, s, off);
    if (lane == 0) out[warp] = s + bd[0];
}

extern "C" void kernel_launch(void* const* d_in, const int* in_sizes, int n_in,
                              void* d_out, int out_size)
{
    const float* inputs = (const float*)d_in[0];
    const float* W1  = (const float*)d_in[1];
    const float* Uh1 = (const float*)d_in[2];
    const float* b1  = (const float*)d_in[3];
    const float* W2  = (const float*)d_in[4];
    const float* Uh2 = (const float*)d_in[5];
    const float* b2  = (const float*)d_in[6];
    const float* Wd  = (const float*)d_in[7];
    const float* bd  = (const float*)d_in[8];
    float* out = (float*)d_out;

    zero_state<<<(HS / 4) / 256, 256>>>();

    dim3 grid(U_ / BU, B_ / BM);   // (16, 8) = 128 blocks
    for (int t = 0; t < T_; t++) {
        const int cur = t & 1;
        // layer 1: x = inputs[:, t, :] (row stride T*D), x K-tiles = 64/16
        lstm_step<<<grid, NT>>>(inputs + (size_t)t * D_, T_ * D_, D_ / BK,
                                W1, Uh1, b1, 1, cur);
        // layer 2: x = h1 just written (selected inside), x K-tiles = 512/16
        lstm_step<<<grid, NT>>>(nullptr, U_, U_ / BK,
                                W2, Uh2, b2, 2, cur);
    }
    dense_head<<<(B_ * 32) / 256, 256>>>(Wd, bd, out);
}

// round 4
// speedup vs baseline: 1.5905x; 1.0139x over previous
#include <cuda_runtime.h>
#include <math.h>

// Problem dims
#define B_   1024
#define T_   256
#define D_   64
#define U_   512
#define HS   (B_*U_)
#define N4   (4*U_)      // 2048 gate columns

// Tile config: 128 blocks of 512 threads; per-thread 8 rows x 1 unit x 4 gates
#define BM 128
#define BU 32
#define BK 16
#define NT 512
#define NBLK 128

// Persistent state (device globals — no allocations allowed)
__device__ float g_h1[2*HS];
__device__ float g_c1[HS];
__device__ float g_h2[2*HS];
__device__ float g_c2[HS];

// Software grid barrier (monotonic generation; reset each replay by init kernel)
__device__ unsigned g_count;
__device__ volatile unsigned g_gen;

__device__ __forceinline__ void grid_sync(unsigned gen)
{
    __syncthreads();
    if (threadIdx.x == 0) {
        __threadfence();                       // publish this block's writes
        unsigned prev = atomicAdd(&g_count, 1u);
        if (prev == gen * NBLK - 1u) {
            __threadfence();
            g_gen = gen;                       // release
        } else {
            while (g_gen < gen) { }            // volatile spin
            __threadfence();                   // acquire
        }
    }
    __syncthreads();
}

__device__ __forceinline__ float sigmoidf_(float x) {
    return 1.0f / (1.0f + __expf(-x));
}
__device__ __forceinline__ float tanhf_(float x) {
    float y;
    asm("tanh.approx.f32 %0, %1;" : "=f"(y) : "f"(x));
    return y;
}

// Packed fp32x2 FMA (Blackwell FFMA2) and 32->64 duplicate pack
#define FMA2(d, a, b) asm("fma.rn.f32x2 %0, %1, %2, %0;" : "+l"(d) : "l"(a), "l"(b))
#define DUP2(d, x)    asm("mov.b64 %0, {%1, %1};" : "=l"(d) : "r"(__float_as_uint(x)))

// One LSTM layer-step tile: z = x@W + hprev@Uh + b; cell update; writes hout, c.
__device__ __forceinline__ void lstm_tile(
    const float* __restrict__ x, int xld, int x_tiles,
    const float* __restrict__ hprev,
    const float* __restrict__ W,
    const float* __restrict__ Uh,
    const float* __restrict__ bias,
    float* __restrict__ cptr,
    float* __restrict__ hout,
    int m0, int u0, int tid,
    float (&sA)[2][BK][BM],
    float (&sB)[2][BK][4][BU])
{
    const int tx  = tid & 31;             // unit within BU
    const int ty  = tid >> 5;             // row group (0..15), 8 rows each
    const int n_tiles = x_tiles + U_ / BK;

    // Conflict-free stage-load index fields:
    const int am  = tid & 127;            // A: row (lane-consecutive STS.32)
    const int akq = tid >> 7;             // A: k-quad 0..3
    const int buq = tid & 7;              // B: warp covers one k row, contig STS.128
    const int bgt = (tid >> 3) & 3;
    const int bkr = tid >> 5;

    unsigned long long acc[4][4];
    #pragma unroll
    for (int i = 0; i < 4; i++)
        #pragma unroll
        for (int j = 0; j < 4; j++) acc[i][j] = 0ull;

    float4 ra, rb;

    auto gload = [&](int tile) {
        const float* A; const float* Wt; int lda, kb;
        if (tile < x_tiles) { A = x;     Wt = W;  lda = xld; kb = tile * BK; }
        else                { A = hprev; Wt = Uh; lda = U_;  kb = (tile - x_tiles) * BK; }
        ra = *reinterpret_cast<const float4*>(&A[(size_t)(m0 + am) * lda + kb + 4 * akq]);
        rb = *reinterpret_cast<const float4*>(&Wt[(size_t)(kb + bkr) * N4 + bgt * U_ + u0 + 4 * buq]);
    };
    auto sstore = [&](int buf) {
        sA[buf][4*akq+0][am] = ra.x;
        sA[buf][4*akq+1][am] = ra.y;
        sA[buf][4*akq+2][am] = ra.z;
        sA[buf][4*akq+3][am] = ra.w;
        *reinterpret_cast<float4*>(&sB[buf][bkr][bgt][4*buq]) = rb;
    };
    auto compute = [&](int buf) {
        #pragma unroll
        for (int k = 0; k < BK; k++) {
            ulonglong2 aL = *reinterpret_cast<const ulonglong2*>(&sA[buf][k][8*ty]);
            ulonglong2 aH = *reinterpret_cast<const ulonglong2*>(&sA[buf][k][8*ty + 4]);
            unsigned long long b0, b1, b2, b3;
            DUP2(b0, sB[buf][k][0][tx]);
            DUP2(b1, sB[buf][k][1][tx]);
            DUP2(b2, sB[buf][k][2][tx]);
            DUP2(b3, sB[buf][k][3][tx]);
            FMA2(acc[0][0], aL.x, b0); FMA2(acc[0][1], aL.x, b1);
            FMA2(acc[0][2], aL.x, b2); FMA2(acc[0][3], aL.x, b3);
            FMA2(acc[1][0], aL.y, b0); FMA2(acc[1][1], aL.y, b1);
            FMA2(acc[1][2], aL.y, b2); FMA2(acc[1][3], aL.y, b3);
            FMA2(acc[2][0], aH.x, b0); FMA2(acc[2][1], aH.x, b1);
            FMA2(acc[2][2], aH.x, b2); FMA2(acc[2][3], aH.x, b3);
            FMA2(acc[3][0], aH.y, b0); FMA2(acc[3][1], aH.y, b1);
            FMA2(acc[3][2], aH.y, b2); FMA2(acc[3][3], aH.y, b3);
        }
    };

    gload(0);
    sstore(0);
    __syncthreads();
    int buf = 0;
    for (int t = 0; t < n_tiles; t++) {
        if (t + 1 < n_tiles) {
            gload(t + 1);
            compute(buf);
            __syncthreads();        // everyone done reading buf^1
            sstore(buf ^ 1);
            __syncthreads();        // stores visible before next compute
            buf ^= 1;
        } else {
            compute(buf);
        }
    }

    // Epilogue: LSTM cell update
    const int u = u0 + tx;
    const float bi_ = bias[u];
    const float bf_ = bias[U_ + u];
    const float bg_ = bias[2 * U_ + u];
    const float bo_ = bias[3 * U_ + u];
    #pragma unroll
    for (int rp = 0; rp < 4; rp++) {
        unsigned zi0, zi1, zf0, zf1, zg0, zg1, zo0, zo1;
        asm("mov.b64 {%0, %1}, %2;" : "=r"(zi0), "=r"(zi1) : "l"(acc[rp][0]));
        asm("mov.b64 {%0, %1}, %2;" : "=r"(zf0), "=r"(zf1) : "l"(acc[rp][1]));
        asm("mov.b64 {%0, %1}, %2;" : "=r"(zg0), "=r"(zg1) : "l"(acc[rp][2]));
        asm("mov.b64 {%0, %1}, %2;" : "=r"(zo0), "=r"(zo1) : "l"(acc[rp][3]));
        #pragma unroll
        for (int h = 0; h < 2; h++) {
            float zi = __uint_as_float(h ? zi1 : zi0) + bi_;
            float zf = __uint_as_float(h ? zf1 : zf0) + bf_;
            float zg = __uint_as_float(h ? zg1 : zg0) + bg_;
            float zo = __uint_as_float(h ? zo1 : zo0) + bo_;
            const int m = m0 + 8 * ty + 2 * rp + h;
            const size_t idx = (size_t)m * U_ + u;
            float c_old = cptr[idx];
            float c_new = sigmoidf_(zf) * c_old + sigmoidf_(zi) * tanhf_(zg);
            cptr[idx] = c_new;
            hout[idx] = sigmoidf_(zo) * tanhf_(c_new);
        }
    }
    // ensure all threads finished reading smem before caller reuses it next layer
    __syncthreads();
}

// Persistent kernel: all 256 timesteps x 2 layers + dense head, one launch.
__global__ __launch_bounds__(NT, 1)
void lstm_persistent(const float* __restrict__ inputs,
                     const float* __restrict__ W1, const float* __restrict__ Uh1,
                     const float* __restrict__ b1,
                     const float* __restrict__ W2, const float* __restrict__ Uh2,
                     const float* __restrict__ b2,
                     const float* __restrict__ Wd, const float* __restrict__ bd,
                     float* __restrict__ out)
{
    __shared__ float sA[2][BK][BM];
    __shared__ float sB[2][BK][4][BU];

    const int tid = threadIdx.x;
    const int u0  = (blockIdx.x & 15) * BU;
    const int m0  = (blockIdx.x >> 4) * BM;

    unsigned gen = 0;
    for (int t = 0; t < T_; t++) {
        const int cur = t & 1;
        // layer 1: x = inputs[:, t, :] (row stride T*D)
        lstm_tile(inputs + (size_t)t * D_, T_ * D_, D_ / BK,
                  g_h1 + (size_t)cur * HS, W1, Uh1, b1,
                  g_c1, g_h1 + (size_t)(cur ^ 1) * HS,
                  m0, u0, tid, sA, sB);
        grid_sync(++gen);
        // layer 2: x = h1 just written (buffer cur^1)
        lstm_tile(g_h1 + (size_t)(cur ^ 1) * HS, U_, U_ / BK,
                  g_h2 + (size_t)cur * HS, W2, Uh2, b2,
                  g_c2, g_h2 + (size_t)(cur ^ 1) * HS,
                  m0, u0, tid, sA, sB);
        grid_sync(++gen);
    }

    // Dense head: final h2 in buffer 0. 2048 warps; first 1024 take one row each.
    const int w = blockIdx.x * (NT / 32) + (tid >> 5);
    const int lane = tid & 31;
    if (w < B_) {
        const float* h = g_h2 + (size_t)w * U_;
        float s = 0.f;
        #pragma unroll
        for (int k = lane; k < U_; k += 32) s += h[k] * Wd[k];
        #pragma unroll
        for (int off = 16; off; off >>= 1) s += __shfl_down_sync(0xffffffffu, s, off);
        if (lane == 0) out[w] = s + bd[0];
    }
}

// Zero state + barrier words every replay (graph determinism)
__global__ void init_state()
{
    const int i = blockIdx.x * blockDim.x + threadIdx.x;   // HS/4 lanes
    float4 z = make_float4(0.f, 0.f, 0.f, 0.f);
    reinterpret_cast<float4*>(g_h1)[i] = z;                // buffer 0
    reinterpret_cast<float4*>(g_c1)[i] = z;
    reinterpret_cast<float4*>(g_h2)[i] = z;                // buffer 0
    reinterpret_cast<float4*>(g_c2)[i] = z;
    if (i == 0) { g_count = 0; g_gen = 0; }
}

extern "C" void kernel_launch(void* const* d_in, const int* in_sizes, int n_in,
                              void* d_out, int out_size)
{
    const float* inputs = (const float*)d_in[0];
    const float* W1  = (const float*)d_in[1];
    const float* Uh1 = (const float*)d_in[2];
    const float* b1  = (const float*)d_in[3];
    const float* W2  = (const float*)d_in[4];
    const float* Uh2 = (const float*)d_in[5];
    const float* b2  = (const float*)d_in[6];
    const float* Wd  = (const float*)d_in[7];
    const float* bd  = (const float*)d_in[8];
    float* out = (float*)d_out;

    init_state<<<(HS / 4) / 256, 256>>>();
    lstm_persistent<<<NBLK, NT>>>(inputs, W1, Uh1, b1, W2, Uh2, b2, Wd, bd, out);
}

// round 8
// speedup vs baseline: 2.1020x; 1.3216x over previous
#include <cuda_runtime.h>
#include <cuda_bf16.h>
#include <cstdint>

// Problem dims
#define B_   1024
#define T_   256
#define D_   64
#define U_   512
#define HS   (B_*U_)
#define NG   2048          // 4*U_ gate columns (n' = 4u+g interleaved)
#define K1   (D_ + U_)     // 576
#define K2   (2*U_)        // 1024
#define KT1  (K1/32)       // 18 k-tiles per split segment
#define KT2  (K2/32)       // 32

#define NT   256
#define NBLK 128
#define RP   40            // padded smem row stride (bf16 elems) = 80B, conflict-free

// ---------------- device globals (no allocations allowed) ----------------
// Pre-split, transposed, gate-interleaved weights: g_B*[n'*K + k], n' = 4u+g
__device__ __align__(16) __nv_bfloat16 g_B1h[NG*K1], g_B1l[NG*K1];
__device__ __align__(16) __nv_bfloat16 g_B2h[NG*K2], g_B2l[NG*K2];
// x split, layout [t][m][64]
__device__ __align__(16) __nv_bfloat16 g_xh[T_*B_*D_], g_xl[T_*B_*D_];
// h ping-pong splits, c states, final h2 fp32
__device__ __align__(16) __nv_bfloat16 g_h1h[2*HS], g_h1l[2*HS];
__device__ __align__(16) __nv_bfloat16 g_h2h[2*HS], g_h2l[2*HS];
__device__ __align__(16) float g_c1[HS], g_c2[HS], g_h2f[HS];

// Software grid barrier (monotonic generation; reset each replay)
__device__ unsigned g_count;
__device__ volatile unsigned g_gen;

__device__ __forceinline__ void grid_sync(unsigned gen)
{
    __syncthreads();
    if (threadIdx.x == 0) {
        __threadfence();
        unsigned prev = atomicAdd(&g_count, 1u);
        if (prev == gen * NBLK - 1u) {
            __threadfence();
            g_gen = gen;
        } else {
            while (g_gen < gen) { }
            __threadfence();
        }
    }
    __syncthreads();
}

__device__ __forceinline__ float sigmoidf_(float x) { return 1.0f / (1.0f + __expf(-x)); }
__device__ __forceinline__ float tanhf_(float x) {
    float y; asm("tanh.approx.f32 %0, %1;" : "=f"(y) : "f"(x)); return y;
}
__device__ __forceinline__ uint32_t smem_u32(const void* p) {
    return (uint32_t)__cvta_generic_to_shared(p);
}

#define LDSM4(r0, r1, r2, r3, addr) \
    asm volatile("ldmatrix.sync.aligned.m8n8.x4.shared.b16 {%0,%1,%2,%3}, [%4];" \
        : "=r"(r0), "=r"(r1), "=r"(r2), "=r"(r3) : "r"(addr))

#define MMA16816(c, a, b0_, b1_) \
    asm volatile("mma.sync.aligned.m16n8k16.row.col.f32.bf16.bf16.f32 " \
        "{%0,%1,%2,%3}, {%4,%5,%6,%7}, {%8,%9}, {%0,%1,%2,%3};" \
        : "+f"((c)[0]), "+f"((c)[1]), "+f"((c)[2]), "+f"((c)[3]) \
        : "r"((a)[0]), "r"((a)[1]), "r"((a)[2]), "r"((a)[3]), "r"(b0_), "r"(b1_))

// ---------------- one layer-step (GEMM over 3 bf16-split segments + cell) ----
__device__ __forceinline__ void layer_step(
    int ktiles, int s0_len, int s0_stride,
    const __nv_bfloat16* __restrict__ a0h, const __nv_bfloat16* __restrict__ a0l,
    const __nv_bfloat16* __restrict__ a1h, const __nv_bfloat16* __restrict__ a1l,
    const __nv_bfloat16* __restrict__ Bh,  const __nv_bfloat16* __restrict__ Bl, int Krow,
    const float* __restrict__ bias, float* __restrict__ cst,
    __nv_bfloat16* __restrict__ outh, __nv_bfloat16* __restrict__ outl,
    float* __restrict__ h2f,
    int m0, int n0, int u0, int tid,
    __nv_bfloat16 (&sA)[2][128*RP], __nv_bfloat16 (&sB)[2][128*RP])
{
    const int lane = tid & 31;
    const int ww   = tid >> 5;
    const int wm   = ww & 3;          // m group (32 rows)
    const int wn   = ww >> 2;         // n group (64 n' cols)
    const int n_tiles = 3 * ktiles;

    float acc[2][8][4];
    #pragma unroll
    for (int i = 0; i < 2; i++)
        #pragma unroll
        for (int j = 0; j < 8; j++)
            #pragma unroll
            for (int q = 0; q < 4; q++) acc[i][j][q] = 0.f;

    // hoisted ldmatrix address parts (bytes)
    const uint32_t aoff = ((wm * 32 + (lane & 15)) * RP + ((lane >> 4) << 3)) * 2;
    const uint32_t boff = ((wn * 64 + (lane & 15)) * RP + ((lane >> 4) << 3)) * 2;
    const uint32_t sAu0 = smem_u32(&sA[0][0]), sAu1 = smem_u32(&sA[1][0]);
    const uint32_t sBu0 = smem_u32(&sB[0][0]), sBu1 = smem_u32(&sB[1][0]);

    uint4 ra[2], rb[2];

    auto gload = [&](int tile) {
        const int seg = (tile >= ktiles) + (tile >= 2 * ktiles);
        const int kb  = (tile - seg * ktiles) * 32;
        const bool hi = (seg < 2);
        const __nv_bfloat16* Bs = (seg == 1) ? Bl : Bh;
        #pragma unroll
        for (int i = 0; i < 2; i++) {
            const int c   = tid + i * NT;
            const int row = c >> 2;
            const int k   = kb + (c & 3) * 8;
            const __nv_bfloat16* As; size_t ao;
            if (k < s0_len) { As = hi ? a0h : a0l; ao = (size_t)(m0 + row) * s0_stride + k; }
            else            { As = hi ? a1h : a1l; ao = (size_t)(m0 + row) * U_ + (k - s0_len); }
            ra[i] = *reinterpret_cast<const uint4*>(As + ao);
            rb[i] = *reinterpret_cast<const uint4*>(Bs + (size_t)(n0 + row) * Krow + k);
        }
    };
    auto sstore = [&](int buf) {
        #pragma unroll
        for (int i = 0; i < 2; i++) {
            const int c   = tid + i * NT;
            const int row = c >> 2;
            const int ks  = (c & 3) * 8;
            *reinterpret_cast<uint4*>(&sA[buf][row * RP + ks]) = ra[i];
            *reinterpret_cast<uint4*>(&sB[buf][row * RP + ks]) = rb[i];
        }
    };
    auto compute = [&](int buf) {
        const uint32_t sa = (buf ? sAu1 : sAu0) + aoff;
        const uint32_t sb = (buf ? sBu1 : sBu0) + boff;
        #pragma unroll
        for (int kk = 0; kk < 32; kk += 16) {
            uint32_t a[2][4], b[4][4];
            #pragma unroll
            for (int mf = 0; mf < 2; mf++)
                LDSM4(a[mf][0], a[mf][1], a[mf][2], a[mf][3],
                      sa + (mf * 16 * RP + kk) * 2);
            #pragma unroll
            for (int nfp = 0; nfp < 4; nfp++)
                LDSM4(b[nfp][0], b[nfp][1], b[nfp][2], b[nfp][3],
                      sb + (nfp * 16 * RP + kk) * 2);
            #pragma unroll
            for (int mf = 0; mf < 2; mf++)
                #pragma unroll
                for (int nfp = 0; nfp < 4; nfp++) {
                    MMA16816(acc[mf][2 * nfp],     a[mf], b[nfp][0], b[nfp][2]);
                    MMA16816(acc[mf][2 * nfp + 1], a[mf], b[nfp][1], b[nfp][3]);
                }
        }
    };

    gload(0);
    sstore(0);
    __syncthreads();
    int buf = 0;
    for (int t = 0; t < n_tiles; t++) {
        if (t + 1 < n_tiles) {
            gload(t + 1);
            compute(buf);
            __syncthreads();
            sstore(buf ^ 1);
            __syncthreads();
            buf ^= 1;
        } else {
            compute(buf);
        }
    }

    // Epilogue: pair lanes (lane^1) to assemble all 4 gates of a unit.
    // even lane handles row r (i,f own / g,o from partner); odd handles row r+8.
    #pragma unroll
    for (int mf = 0; mf < 2; mf++) {
        const int rbase = m0 + wm * 32 + mf * 16 + (lane >> 2) + 8 * (lane & 1);
        #pragma unroll
        for (int nf = 0; nf < 8; nf++) {
            float c0 = acc[mf][nf][0], c1 = acc[mf][nf][1];
            float c2 = acc[mf][nf][2], c3 = acc[mf][nf][3];
            float p0 = __shfl_xor_sync(0xffffffffu, c0, 1);
            float p1 = __shfl_xor_sync(0xffffffffu, c1, 1);
            float p2 = __shfl_xor_sync(0xffffffffu, c2, 1);
            float p3 = __shfl_xor_sync(0xffffffffu, c3, 1);
            float zi, zf, zg, zo;
            if ((lane & 1) == 0) { zi = c0; zf = c1; zg = p0; zo = p1; }
            else                 { zi = p2; zf = p3; zg = c2; zo = c3; }
            const int u = u0 + wn * 16 + nf * 2 + ((lane & 3) >> 1);
            zi += bias[u];
            zf += bias[U_ + u];
            zg += bias[2 * U_ + u];
            zo += bias[3 * U_ + u];
            const size_t gi = (size_t)rbase * U_ + u;
            const float cold = cst[gi];
            const float cn = sigmoidf_(zf) * cold + sigmoidf_(zi) * tanhf_(zg);
            const float hv = sigmoidf_(zo) * tanhf_(cn);
            cst[gi] = cn;
            const __nv_bfloat16 hh = __float2bfloat16(hv);
            outh[gi] = hh;
            outl[gi] = __float2bfloat16(hv - __bfloat162float(hh));
            if (h2f) h2f[gi] = hv;
        }
    }
}

// ---------------- persistent kernel: 256 steps x 2 layers + dense head ------
__global__ __launch_bounds__(NT, 1)
void lstm_persistent(const float* __restrict__ b1, const float* __restrict__ b2,
                     const float* __restrict__ Wd, const float* __restrict__ bd,
                     float* __restrict__ out)
{
    __shared__ __nv_bfloat16 sA[2][128*RP];
    __shared__ __nv_bfloat16 sB[2][128*RP];

    const int tid = threadIdx.x;
    const int n0  = (blockIdx.x & 15) * 128;
    const int m0  = (blockIdx.x >> 4) * 128;
    const int u0  = (blockIdx.x & 15) * 32;

    unsigned gen = 0;
    for (int t = 0; t < T_; t++) {
        const int cur = t & 1;
        layer_step(KT1, D_, D_,
                   g_xh + (size_t)t * (B_ * D_), g_xl + (size_t)t * (B_ * D_),
                   g_h1h + (size_t)cur * HS, g_h1l + (size_t)cur * HS,
                   g_B1h, g_B1l, K1, b1, g_c1,
                   g_h1h + (size_t)(cur ^ 1) * HS, g_h1l + (size_t)(cur ^ 1) * HS,
                   nullptr, m0, n0, u0, tid, sA, sB);
        grid_sync(++gen);
        layer_step(KT2, U_, U_,
                   g_h1h + (size_t)(cur ^ 1) * HS, g_h1l + (size_t)(cur ^ 1) * HS,
                   g_h2h + (size_t)cur * HS, g_h2l + (size_t)cur * HS,
                   g_B2h, g_B2l, K2, b2, g_c2,
                   g_h2h + (size_t)(cur ^ 1) * HS, g_h2l + (size_t)(cur ^ 1) * HS,
                   g_h2f, m0, n0, u0, tid, sA, sB);
        grid_sync(++gen);
    }

    // Dense head: 128 blocks x 8 warps = 1024 warps, one batch row each.
    const int w = blockIdx.x * (NT / 32) + (tid >> 5);
    const int lane = tid & 31;
    const float* h = g_h2f + (size_t)w * U_;
    float s = 0.f;
    #pragma unroll
    for (int k = lane; k < U_; k += 32) s += h[k] * Wd[k];
    #pragma unroll
    for (int off = 16; off; off >>= 1) s += __shfl_down_sync(0xffffffffu, s, off);
    if (lane == 0) out[w] = s + bd[0];
}

// ---------------- prep kernels (deterministic, run every replay) ------------
__global__ void prep_weights(const float* __restrict__ W1, const float* __restrict__ Uh1,
                             const float* __restrict__ W2, const float* __restrict__ Uh2)
{
    const long total1 = (long)NG * K1;
    const long total  = total1 + (long)NG * K2;
    for (long idx = blockIdx.x * (long)blockDim.x + threadIdx.x; idx < total;
         idx += (long)gridDim.x * blockDim.x) {
        if (idx < total1) {
            const int np = (int)(idx / K1), k = (int)(idx % K1);
            const int n = ((np & 3) << 9) | (np >> 2);
            const float v = (k < D_) ? W1[(size_t)k * NG + n] : Uh1[(size_t)(k - D_) * NG + n];
            const __nv_bfloat16 hi = __float2bfloat16(v);
            g_B1h[idx] = hi;
            g_B1l[idx] = __float2bfloat16(v - __bfloat162float(hi));
        } else {
            const long i2 = idx - total1;
            const int np = (int)(i2 / K2), k = (int)(i2 % K2);
            const int n = ((np & 3) << 9) | (np >> 2);
            const float v = (k < U_) ? W2[(size_t)k * NG + n] : Uh2[(size_t)(k - U_) * NG + n];
            const __nv_bfloat16 hi = __float2bfloat16(v);
            g_B2h[i2] = hi;
            g_B2l[i2] = __float2bfloat16(v - __bfloat162float(hi));
        }
    }
}

__global__ void prep_x(const float* __restrict__ inputs)
{
    const long total = (long)T_ * B_ * D_;
    for (long idx = blockIdx.x * (long)blockDim.x + threadIdx.x; idx < total;
         idx += (long)gridDim.x * blockDim.x) {
        const int k = (int)(idx & 63);
        const int m = (int)((idx >> 6) & 1023);
        const int t = (int)(idx >> 16);
        const float v = inputs[(size_t)m * (T_ * D_) + (size_t)t * D_ + k];
        const __nv_bfloat16 hi = __float2bfloat16(v);
        g_xh[idx] = hi;
        g_xl[idx] = __float2bfloat16(v - __bfloat162float(hi));
    }
}

__global__ void init_state()
{
    const int i = blockIdx.x * blockDim.x + threadIdx.x;   // HS threads
    const __nv_bfloat16 z = __float2bfloat16(0.f);
    g_h1h[i] = z; g_h1l[i] = z;      // buffer 0
    g_h2h[i] = z; g_h2l[i] = z;
    g_c1[i] = 0.f; g_c2[i] = 0.f;
    if (i == 0) { g_count = 0; g_gen = 0; }
}

extern "C" void kernel_launch(void* const* d_in, const int* in_sizes, int n_in,
                              void* d_out, int out_size)
{
    const float* inputs = (const float*)d_in[0];
    const float* W1  = (const float*)d_in[1];
    const float* Uh1 = (const float*)d_in[2];
    const float* b1  = (const float*)d_in[3];
    const float* W2  = (const float*)d_in[4];
    const float* Uh2 = (const float*)d_in[5];
    const float* b2  = (const float*)d_in[6];
    const float* Wd  = (const float*)d_in[7];
    const float* bd  = (const float*)d_in[8];
    float* out = (float*)d_out;

    prep_weights<<<2048, 256>>>(W1, Uh1, W2, Uh2);
    prep_x<<<4096, 256>>>(inputs);
    init_state<<<HS / 256, 256>>>();
    lstm_persistent<<<NBLK, NT>>>(b1, b2, Wd, bd, out);
}